// round 15
// baseline (speedup 1.0000x reference)
#include <cuda_runtime.h>
#include <cuda_fp16.h>
#include <cstdint>

// ---------------- problem constants ----------------
#define NHEADS 16
#define CDIM   512
#define HD     32
#define NTOK   64
#define NWIN   2048
#define NROWS  (NWIN * NTOK)

// ---------------- scratch ----------------
__device__ __align__(256) __half g_q16[(size_t)NWIN * NHEADS * NTOK * HD];
__device__ __align__(256) __half g_k16[(size_t)NWIN * NHEADS * NTOK * HD];
__device__ __align__(256) __half g_vt[(size_t)NWIN * NHEADS * NTOK * HD];

__device__ __align__(256) __half g_x16[(size_t)NROWS * CDIM];   // x fp16
__device__ __align__(256) __half g_ao16[(size_t)NROWS * CDIM];  // attn out fp16
__device__ __align__(256) __half g_wt16[1536 * 512];   // qkv_w^T fp16 [n][k]
__device__ __align__(256) __half g_pt16[512 * 512];    // proj_w^T fp16 [n][k]

// ---------------- helpers ----------------
__device__ __forceinline__ unsigned h2u(__half2 h) {
    return *reinterpret_cast<unsigned*>(&h);
}
__device__ __forceinline__ void mma_f16(float c[4], const unsigned a[4], const unsigned b[2]) {
    asm volatile(
        "mma.sync.aligned.m16n8k16.row.col.f32.f16.f16.f32 "
        "{%0,%1,%2,%3},{%4,%5,%6,%7},{%8,%9},{%0,%1,%2,%3};\n"
        : "+f"(c[0]), "+f"(c[1]), "+f"(c[2]), "+f"(c[3])
        : "r"(a[0]), "r"(a[1]), "r"(a[2]), "r"(a[3]), "r"(b[0]), "r"(b[1]));
}
__device__ __forceinline__ void lm4(unsigned r[4], uint32_t addr) {
    asm volatile("ldmatrix.sync.aligned.m8n8.x4.shared.b16 {%0,%1,%2,%3}, [%4];"
                 : "=r"(r[0]), "=r"(r[1]), "=r"(r[2]), "=r"(r[3]) : "r"(addr));
}
__device__ __forceinline__ void cpa16(uint32_t dst, const void* src) {
    asm volatile("cp.async.cg.shared.global [%0], [%1], 16;\n" :: "r"(dst), "l"(src));
}
__device__ __forceinline__ long xrow(int widx, int n) {
    int b  = widx >> 8;
    int hy = (widx >> 4) & 15;
    int wx = widx & 15;
    int h  = hy * 8 + (n >> 3);
    int w  = wx * 8 + (n & 7);
    return ((long)((b << 7) + h) << 7) + w;
}

// ---------------- prep kernels ----------------
__global__ __launch_bounds__(256) void split_x_kernel(const float* __restrict__ x) {
    size_t i = (size_t)blockIdx.x * 256 + threadIdx.x;
    float4 v = reinterpret_cast<const float4*>(x)[i];
    reinterpret_cast<__half2*>(g_x16)[2 * i + 0] =
        __halves2half2(__float2half_rn(v.x), __float2half_rn(v.y));
    reinterpret_cast<__half2*>(g_x16)[2 * i + 1] =
        __halves2half2(__float2half_rn(v.z), __float2half_rn(v.w));
}
template <int WSEL>
__global__ __launch_bounds__(256) void split_w_kernel(const float* __restrict__ W) {
    constexpr int N = (WSEL == 0) ? 1536 : 512;
    int idx = blockIdx.x * 256 + threadIdx.x;
    int n = idx >> 9, k = idx & 511;
    float v = W[(size_t)k * N + n];
    if (WSEL == 0) g_wt16[idx] = __float2half_rn(v);
    else           g_pt16[idx] = __float2half_rn(v);
}

// ---------------- fp16 single-term GEMM, wide warp tile ----------------
// CTA tile M=64 x N=256, Ktile=32, 256 threads (8 warps 2x4, warp tile 32x64).
// Flat 4-stage cp.async pipeline. Stage 20KB: A [0,4K) B [4K,20K).
// Per k16 step/warp: 6 lm4 feed 16 mma (266B L1 per mma, was 344).
#define STAGE_B 20480u
#define GEMM_SMEM (4 * 20480)

template <int MODE>   // 0: QKV (NT=6), 1: proj (NT=2)
__global__ __launch_bounds__(256, 2) void gemm_lm(
    const float* __restrict__ bias, float* __restrict__ out)
{
    constexpr int NT = (MODE == 0) ? 6 : 2;
    constexpr int L  = NT * 16;

    extern __shared__ __align__(128) char dyn[];
    const uint32_t smem0 = (uint32_t)__cvta_generic_to_shared(dyn);

    const int bx   = blockIdx.x;
    const int tid  = threadIdx.x;
    const int wid  = tid >> 5, lane = tid & 31;
    const int g    = lane >> 2, t4 = lane & 3;
    const int wm   = wid & 1, wn = wid >> 1;

    const __half* AP = (MODE == 0) ? g_x16 : g_ao16;
    const __half* BP = (MODE == 0) ? g_wt16 : g_pt16;

    // ---- cp.async tasks: 256 A (1/thread) + 1024 B (4/thread), 16B each ----
    const __half* aPtr; uint32_t aDst;
    {
        int row = tid >> 2, ch = tid & 3;
        long rowb = (MODE == 0) ? xrow(bx, row) * 512L
                                : ((long)bx * 64 + row) * 512L;
        aPtr = AP + rowb + ch * 8;
        aDst = row * 64u + (((uint32_t)(ch ^ ((row >> 1) & 3))) << 4);
    }
    const __half* bPtr[4]; uint32_t bDst[4];
#pragma unroll
    for (int i = 0; i < 4; i++) {
        int idx = tid + i * 256;
        int row = idx >> 2, ch = idx & 3;
        bPtr[i] = BP + (size_t)row * 512 + ch * 8;
        bDst[i] = 4096u + row * 64u + (((uint32_t)(ch ^ ((row >> 1) & 3))) << 4);
    }

    // ---- ldmatrix per-lane base offsets ----
    const int rowA = wm * 32 + (lane & 15);
    const int cbA  = (lane >> 4) & 1;
    const uint32_t aLane = rowA * 64u + (((uint32_t)(cbA ^ ((rowA >> 1) & 3))) << 4);
    const int rowB = wn * 64 + (lane & 7) + (((lane >> 4) & 1) << 3);
    const int cbB  = (lane >> 3) & 1;
    const uint32_t bLane = 4096u + rowB * 64u +
                           (((uint32_t)(cbB ^ ((rowB >> 1) & 3))) << 4);

    const float2* bias2 = reinterpret_cast<const float2*>(bias);

    float acc[2][8][4];
#pragma unroll
    for (int a = 0; a < 2; a++)
#pragma unroll
        for (int b = 0; b < 8; b++)
#pragma unroll
            for (int cc = 0; cc < 4; cc++) acc[a][b][cc] = 0.f;

    // prologue: chunks 0,1,2 into stages 0,1,2
#pragma unroll
    for (int s = 0; s < 3; s++) {
        uint32_t sb = smem0 + s * STAGE_B;
        cpa16(sb + aDst, aPtr + s * 32);
#pragma unroll
        for (int i = 0; i < 4; i++) cpa16(sb + bDst[i], bPtr[i] + (uint32_t)(s * 32));
        asm volatile("cp.async.commit_group;\n");
    }

    for (int c = 0; c < L; ++c) {
        if (c + 3 < L) asm volatile("cp.async.wait_group 2;\n");
        else           asm volatile("cp.async.wait_group 0;\n");
        __syncthreads();

        // refill chunk c+3 into stage (c+3)&3
        if (c + 3 < L) {
            int cn = c + 3;
            uint32_t sb = smem0 + (uint32_t)(cn & 3) * STAGE_B;
            int aOff = (cn & 15) << 5;
            uint32_t bOff = ((uint32_t)(cn >> 4) * 131072u) + (uint32_t)((cn & 15) << 5);
            cpa16(sb + aDst, aPtr + aOff);
#pragma unroll
            for (int i = 0; i < 4; i++) cpa16(sb + bDst[i], bPtr[i] + bOff);
            asm volatile("cp.async.commit_group;\n");
        }

        // compute chunk c
        const uint32_t sb = smem0 + (uint32_t)(c & 3) * STAGE_B;
        const uint32_t aB0 = sb + aLane;
        const uint32_t bB0 = sb + bLane;
#pragma unroll
        for (int s16 = 0; s16 < 2; s16++) {
            const uint32_t aA = aB0 ^ (s16 << 5);
            const uint32_t bA = bB0 ^ (s16 << 5);
            unsigned Ah[2][4];
            lm4(Ah[0], aA);          lm4(Ah[1], aA + 1024);
#pragma unroll
            for (int ng = 0; ng < 4; ng++) {
                unsigned Bv[4];
                lm4(Bv, bA + ng * 1024);
#pragma unroll
                for (int mi = 0; mi < 2; mi++) {
                    mma_f16(acc[mi][2 * ng + 0], Ah[mi], Bv + 0);
                    mma_f16(acc[mi][2 * ng + 1], Ah[mi], Bv + 2);
                }
            }
        }

        // nt boundary: register-only epilogue + acc reset
        if ((c & 15) == 15) {
            const int nt = c >> 4;
#pragma unroll
            for (int mi = 0; mi < 2; mi++)
#pragma unroll
                for (int ni = 0; ni < 8; ni++) {
                    int col = wn * 64 + ni * 8 + 2 * t4;
                    int co  = nt * 256 + col;
                    float2 bb = __ldg(bias2 + (co >> 1));
#pragma unroll
                    for (int jr = 0; jr < 2; jr++) {
                        int row = wm * 32 + mi * 16 + g + 8 * jr;   // [0,64)
                        float vx = acc[mi][ni][2 * jr + 0] + bb.x;
                        float vy = acc[mi][ni][2 * jr + 1] + bb.y;
                        if (MODE == 0) {
                            int part = co >> 9, head = (co >> 5) & 15, d = co & 31;
                            size_t tokb = ((size_t)(bx * 16 + head) * 64 + row);
                            __half hx = __float2half_rn(vx), hy = __float2half_rn(vy);
                            if (part == 0) {
                                *reinterpret_cast<__half2*>(g_q16 + tokb * 32 + d) =
                                    __halves2half2(hx, hy);
                            } else if (part == 1) {
                                *reinterpret_cast<__half2*>(g_k16 + tokb * 32 + d) =
                                    __halves2half2(hx, hy);
                            } else {                // V: transposed [dim][tok]
                                size_t vb = (size_t)(bx * 16 + head) * 32;
                                g_vt[(vb + d) * 64 + row]     = hx;
                                g_vt[(vb + d + 1) * 64 + row] = hy;
                            }
                        } else {
                            float2 v2; v2.x = vx; v2.y = vy;
                            *reinterpret_cast<float2*>(out + xrow(bx, row) * 512L + co) = v2;
                        }
                    }
                }
#pragma unroll
            for (int a = 0; a < 2; a++)
#pragma unroll
                for (int b = 0; b < 8; b++)
#pragma unroll
                    for (int cc = 0; cc < 4; cc++) acc[a][b][cc] = 0.f;
        }
    }
}

// ---------------- attention: single-term fp16 (unchanged from R14) ----------------
#define S_Q   0u
#define S_K   5120u
#define S_VT  10240u     // 32 rows x 144
#define S_P   14848u     // 64 rows x 144
#define S_RCP 24064u     // 64 floats
#define ATTN_SMEM 24320

__global__ __launch_bounds__(128) void attn_kernel(const float* __restrict__ tbl) {
    __shared__ __align__(16) char sm[ATTN_SMEM];
    const uint32_t sb = (uint32_t)__cvta_generic_to_shared(sm);
    float* sRcp = reinterpret_cast<float*>(sm + S_RCP);

    const int bx   = blockIdx.x;
    const int widx = bx >> 4, head = bx & 15;
    const int tid  = threadIdx.x, wid = tid >> 5, lane = tid & 31;
    const int g    = lane >> 2, t4 = lane & 3;

    const __half* qq = g_q16 + (size_t)bx * 2048;
    const __half* kk = g_k16 + (size_t)bx * 2048;
    const __half* vt = g_vt  + (size_t)bx * 2048;

#pragma unroll
    for (int i = 0; i < 6; i++) {
        int idx = i * 128 + tid;
        if (idx < 512) {
            int arr = idx >> 8;          // 0:q 1:k
            int rem = idx & 255;
            int row = rem >> 2, ch = rem & 3;
            const __half* src = (arr == 0 ? qq : kk) + row * 32 + ch * 8;
            uint32_t base = (arr == 0) ? S_Q : S_K;
            cpa16(sb + base + row * 80 + ch * 16, src);
        } else {
            int rem = idx - 512;
            int r = rem >> 3, ch = rem & 7;
            cpa16(sb + S_VT + r * 144 + ch * 16, vt + r * 64 + ch * 8);
        }
    }
    asm volatile("cp.async.commit_group;\ncp.async.wait_group 0;\n");
    __syncthreads();

    const int r0 = wid * 16;

    float sacc[8][4];
#pragma unroll
    for (int n = 0; n < 8; n++)
#pragma unroll
        for (int j = 0; j < 4; j++) sacc[n][j] = 0.f;

    const uint32_t aQ = sb + S_Q + (r0 + (lane & 15)) * 80 + ((lane >> 4) & 1) * 16;
    const uint32_t bK = sb + S_K + ((lane & 7) + ((lane >> 4) & 1) * 8) * 80 +
                        ((lane >> 3) & 1) * 16;
#pragma unroll
    for (int kc = 0; kc < 2; kc++) {
        unsigned Aq[4];
        lm4(Aq, aQ + kc * 32);
#pragma unroll
        for (int ng = 0; ng < 4; ng++) {
            unsigned Bv[4];
            lm4(Bv, bK + ng * (16 * 80) + kc * 32);
            mma_f16(sacc[2 * ng + 0], Aq, Bv + 0);
            mma_f16(sacc[2 * ng + 1], Aq, Bv + 2);
        }
    }

    const float scale = 0.17677669529663687f;
    float mx[2] = {-1e30f, -1e30f};
#pragma unroll
    for (int ni = 0; ni < 8; ni++)
#pragma unroll
        for (int j = 0; j < 4; j++) {
            int rg = r0 + g + 8 * (j >> 1);
            int c  = ni * 8 + 2 * t4 + (j & 1);
            int idx = ((rg >> 3) - (c >> 3) + 7) * 15 + ((rg & 7) - (c & 7) + 7);
            float v = sacc[ni][j] * scale + __ldg(tbl + idx * 16 + head);
            sacc[ni][j] = v;
            mx[j >> 1] = fmaxf(mx[j >> 1], v);
        }
#pragma unroll
    for (int h = 0; h < 2; h++) {
        mx[h] = fmaxf(mx[h], __shfl_xor_sync(0xffffffffu, mx[h], 1));
        mx[h] = fmaxf(mx[h], __shfl_xor_sync(0xffffffffu, mx[h], 2));
    }
    float sum[2] = {0.f, 0.f};
#pragma unroll
    for (int ni = 0; ni < 8; ni++)
#pragma unroll
        for (int j = 0; j < 4; j++) {
            float e = __expf(sacc[ni][j] - mx[j >> 1]);
            sacc[ni][j] = e;
            sum[j >> 1] += e;
        }
#pragma unroll
    for (int h = 0; h < 2; h++) {
        sum[h] += __shfl_xor_sync(0xffffffffu, sum[h], 1);
        sum[h] += __shfl_xor_sync(0xffffffffu, sum[h], 2);
    }
    if (t4 == 0) {
        sRcp[r0 + g]     = 1.f / sum[0];
        sRcp[r0 + g + 8] = 1.f / sum[1];
    }

#pragma unroll
    for (int ni = 0; ni < 8; ni++)
#pragma unroll
        for (int jr = 0; jr < 2; jr++) {
            int rg = r0 + g + 8 * jr;
            uint32_t off = (uint32_t)rg * 144u + (uint32_t)(ni * 8 + 2 * t4) * 2u;
            unsigned ph = h2u(__halves2half2(
                __float2half_rn(sacc[ni][2 * jr + 0]),
                __float2half_rn(sacc[ni][2 * jr + 1])));
            asm volatile("st.shared.b32 [%0], %1;" :: "r"(sb + S_P + off), "r"(ph) : "memory");
        }
    __syncwarp();

    float oacc[4][4];
#pragma unroll
    for (int n = 0; n < 4; n++)
#pragma unroll
        for (int j = 0; j < 4; j++) oacc[n][j] = 0.f;

    const uint32_t aP = sb + S_P + (r0 + (lane & 15)) * 144 + ((lane >> 4) & 1) * 16;
    const uint32_t bV = sb + S_VT + ((lane & 7) + ((lane >> 4) & 1) * 8) * 144 +
                        ((lane >> 3) & 1) * 16;
#pragma unroll
    for (int kc = 0; kc < 4; kc++) {
        unsigned Ph[4];
        lm4(Ph, aP + kc * 32);
#pragma unroll
        for (int ng = 0; ng < 2; ng++) {
            unsigned Bv[4];
            lm4(Bv, bV + ng * (16 * 144) + kc * 32);
            mma_f16(oacc[2 * ng + 0], Ph, Bv + 0);
            mma_f16(oacc[2 * ng + 1], Ph, Bv + 2);
        }
    }

#pragma unroll
    for (int ni = 0; ni < 4; ni++)
#pragma unroll
        for (int jr = 0; jr < 2; jr++) {
            int rg = r0 + g + 8 * jr;
            float rcp = sRcp[rg];
            float vx = oacc[ni][2 * jr + 0] * rcp;
            float vy = oacc[ni][2 * jr + 1] * rcp;
            int d = ni * 8 + 2 * t4;
            size_t off = ((size_t)widx * 64 + rg) * 512 + head * 32 + d;
            *reinterpret_cast<__half2*>(g_ao16 + off) =
                __halves2half2(__float2half_rn(vx), __float2half_rn(vy));
        }
}

// ---------------- launch ----------------
extern "C" void kernel_launch(void* const* d_in, const int* in_sizes, int n_in,
                              void* d_out, int out_size) {
    const float* x      = (const float*)d_in[0];
    const float* qkv_w  = (const float*)d_in[1];
    const float* qkv_b  = (const float*)d_in[2];
    const float* proj_w = (const float*)d_in[3];
    const float* proj_b = (const float*)d_in[4];
    const float* tbl    = (const float*)d_in[5];
    float* out = (float*)d_out;

    cudaFuncSetAttribute(gemm_lm<0>, cudaFuncAttributeMaxDynamicSharedMemorySize, GEMM_SMEM);
    cudaFuncSetAttribute(gemm_lm<1>, cudaFuncAttributeMaxDynamicSharedMemorySize, GEMM_SMEM);

    split_x_kernel<<<(NROWS * (CDIM / 4)) / 256, 256>>>(x);
    split_w_kernel<0><<<(1536 * 512) / 256, 256>>>(qkv_w);
    split_w_kernel<1><<<(512 * 512) / 256, 256>>>(proj_w);

    gemm_lm<0><<<NWIN, 256, GEMM_SMEM>>>(qkv_b, nullptr);
    attn_kernel<<<NWIN * NHEADS, 128>>>(tbl);
    gemm_lm<1><<<NWIN, 256, GEMM_SMEM>>>(proj_b, out);
}